// round 9
// baseline (speedup 1.0000x reference)
#include <cuda_runtime.h>
#include <cstdint>
#include <math.h>

// Problem constants
constexpr int B_   = 16;
constexpr int H_   = 16;
constexpr int HD_  = 128;
constexpr int D_   = 2048;
constexpr int SPAST = 4096;
constexpr int SPLITS = 8;
constexpr int CHUNK  = 512;   // SPAST / SPLITS
constexpr float SCALING = 0.08838834764831845f;  // 128^-0.5

// GEMV tiling
constexpr int TILE_O  = 16;   // output rows per block
constexpr int TILE_D4 = 32;   // float4s per chunk = 128 dims
constexpr int STAGES  = 5;    // cp.async pipeline depth (40 KB smem)

// Scratch (static device globals — no allocation allowed)
__device__ float g_q[B_ * D_];
__device__ float g_attn[B_ * D_];
__device__ float g_pm[B_ * H_ * SPLITS];
__device__ float g_pl[B_ * H_ * SPLITS];
__device__ float g_pacc[B_ * H_ * SPLITS * HD_];

struct GemvArgs {
    const float* W[3];
    const float* bias[3];
    float*       out[3];
    float        scale[3];
};

__device__ __forceinline__ void cp_async16(unsigned int saddr, const void* g) {
    asm volatile("cp.async.cg.shared.global [%0], [%1], 16;" :: "r"(saddr), "l"(g));
}
__device__ __forceinline__ void cp_commit() {
    asm volatile("cp.async.commit_group;");
}
__device__ __forceinline__ void cp_wait3() {
    asm volatile("cp.async.wait_group 3;");  // STAGES-2
}

// ---------------------------------------------------------------------------
// cp.async smem-pipelined GEMV: out[b,o] (+)= scale * sum_d x[b,d] * W[o,d].
// Weights stream through a 5-stage, 8KB/stage shared-memory pipeline (LDGSTS:
// in-flight bytes live in smem, not registers -> ~100KB/SM in flight instead
// of ~1KB, which is what the DRAM latency*BW product demands).
// Block = 256 threads; warp owns 2 rows x 16 batches; x is L1/L2-hot.
// KSPLIT=1: direct (acc+bias)*scale store.  KSPLIT>1: atomicAdd into
// bias-preseeded output.
// ---------------------------------------------------------------------------
template <int KSPLIT>
__global__ __launch_bounds__(256) void gemv_kernel(const float* __restrict__ x,
                                                   GemvArgs a) {
    __shared__ float4 sw[STAGES][TILE_O][TILE_D4];   // 40 KB

    int tid  = threadIdx.x;
    int warp = tid >> 5;
    int lane = tid & 31;
    int row0 = blockIdx.x * TILE_O;
    int mi   = row0 >> 11;           // which matrix (2048 rows each)
    int o0   = row0 & 2047;

    const float4* W = (const float4*)a.W[mi];
    const float4* X = (const float4*)x;

    constexpr int NCHUNK = 16 / KSPLIT;     // chunks of 128 dims this block does
    const int c0 = blockIdx.y * NCHUNK;     // starting chunk

    // Loader: thread t covers float4 #t and #(t+256) of the 512 per stage.
    auto issue = [&](int c, int stage) {
#pragma unroll
        for (int k = 0; k < 2; k++) {
            int fi = tid + k * 256;
            int r  = fi >> 5;
            int d4 = fi & 31;
            unsigned int sa =
                (unsigned int)__cvta_generic_to_shared(&sw[stage][r][d4]);
            cp_async16(sa, &W[(size_t)(o0 + r) * 512 + (size_t)(c0 + c) * TILE_D4 + d4]);
        }
    };

    float acc[2][16];
#pragma unroll
    for (int r = 0; r < 2; r++)
#pragma unroll
        for (int b = 0; b < 16; b++) acc[r][b] = 0.f;

    // Prologue: fill STAGES-1 stages.
#pragma unroll
    for (int c = 0; c < STAGES - 1; c++) {
        if (c < NCHUNK) issue(c, c);
        cp_commit();
    }

    const int r0 = warp * 2;
    for (int c = 0; c < NCHUNK; c++) {
        cp_wait3();
        __syncthreads();   // chunk c resident; previous iter's compute done
        int stage = c % STAGES;
        float4 w0 = sw[stage][r0 + 0][lane];
        float4 w1 = sw[stage][r0 + 1][lane];
        int xb = (c0 + c) * TILE_D4 + lane;
#pragma unroll
        for (int b = 0; b < 16; b++) {
            float4 xv = X[b * 512 + xb];
            acc[0][b] += w0.x * xv.x + w0.y * xv.y + w0.z * xv.z + w0.w * xv.w;
            acc[1][b] += w1.x * xv.x + w1.y * xv.y + w1.z * xv.z + w1.w * xv.w;
        }
        int cn = c + STAGES - 1;
        if (cn < NCHUNK) issue(cn, cn % STAGES);
        cp_commit();       // empty groups in the tail keep accounting aligned
    }

    // Warp-reduce the 32 partial sums.
#pragma unroll
    for (int r = 0; r < 2; r++)
#pragma unroll
        for (int b = 0; b < 16; b++) {
            float v = acc[r][b];
            v += __shfl_xor_sync(0xffffffffu, v, 16);
            v += __shfl_xor_sync(0xffffffffu, v, 8);
            v += __shfl_xor_sync(0xffffffffu, v, 4);
            v += __shfl_xor_sync(0xffffffffu, v, 2);
            v += __shfl_xor_sync(0xffffffffu, v, 1);
            acc[r][b] = v;
        }

    float* out = a.out[mi];
    float  sc  = a.scale[mi];
    if (KSPLIT == 1) {
        const float* bias = a.bias[mi];
#pragma unroll
        for (int r = 0; r < 2; r++) {
            float bb = bias[o0 + r0 + r];
#pragma unroll
            for (int b = 0; b < 16; b++)
                if (lane == b)
                    out[b * D_ + o0 + r0 + r] = (acc[r][b] + bb) * sc;
        }
    } else {
#pragma unroll
        for (int r = 0; r < 2; r++)
#pragma unroll
            for (int b = 0; b < 16; b++)
                if (lane == b)
                    atomicAdd(&out[b * D_ + o0 + r0 + r], acc[r][b] * sc);
    }
}

// ---------------------------------------------------------------------------
// Split-S flash-decode attention partials (proven structure, untouched).
// grid = (256 bh, 8 splits), block = 256 (8 warps). Warp-per-row online
// softmax; each lane owns 4 head-dim elements (float4).
// K/V are a 1 GB single-use stream: __ldcs keeps them out of L2's way.
// ---------------------------------------------------------------------------
__global__ __launch_bounds__(256) void attn_partial_kernel(
    const float* __restrict__ pk, const float* __restrict__ pv,
    const float* __restrict__ mask,
    const float* __restrict__ knew, const float* __restrict__ vnew) {
    int bh    = blockIdx.x;
    int split = blockIdx.y;
    int b     = bh >> 4;
    int h     = bh & 15;
    int warp  = threadIdx.x >> 5;
    int lane  = threadIdx.x & 31;

    const float4* q4p = (const float4*)(g_q + b * D_ + h * HD_);
    float4 q4 = q4p[lane];  // q pre-scaled by SCALING

    size_t base = ((size_t)b * SPAST) * D_ + h * HD_;

    float  m = -1e30f, l = 0.f;
    float4 acc = make_float4(0.f, 0.f, 0.f, 0.f);

    int s0 = split * CHUNK + warp;
    int s_end = split * CHUNK + CHUNK;

#pragma unroll 4
    for (int s = s0; s < s_end; s += 8) {
        const float4* kr = (const float4*)(pk + base + (size_t)s * D_);
        const float4* vr = (const float4*)(pv + base + (size_t)s * D_);
        float4 k4 = __ldcs(&kr[lane]);
        float4 v4 = __ldcs(&vr[lane]);
        float sc = k4.x * q4.x + k4.y * q4.y + k4.z * q4.z + k4.w * q4.w;
        sc += __shfl_xor_sync(0xffffffffu, sc, 16);
        sc += __shfl_xor_sync(0xffffffffu, sc, 8);
        sc += __shfl_xor_sync(0xffffffffu, sc, 4);
        sc += __shfl_xor_sync(0xffffffffu, sc, 2);
        sc += __shfl_xor_sync(0xffffffffu, sc, 1);
        sc += mask[s];
        float nm   = fmaxf(m, sc);
        float corr = __expf(m - nm);
        float p    = __expf(sc - nm);
        m = nm;
        l = l * corr + p;
        acc.x = acc.x * corr + p * v4.x;
        acc.y = acc.y * corr + p * v4.y;
        acc.z = acc.z * corr + p * v4.z;
        acc.w = acc.w * corr + p * v4.w;
    }

    // The new token (s = 4096) lives in the last split, handled by warp 0.
    if (split == SPLITS - 1 && warp == 0) {
        const float4* kr = (const float4*)(knew + b * D_ + h * HD_);
        const float4* vr = (const float4*)(vnew + b * D_ + h * HD_);
        float4 k4 = kr[lane];
        float4 v4 = vr[lane];
        float sc = k4.x * q4.x + k4.y * q4.y + k4.z * q4.z + k4.w * q4.w;
        sc += __shfl_xor_sync(0xffffffffu, sc, 16);
        sc += __shfl_xor_sync(0xffffffffu, sc, 8);
        sc += __shfl_xor_sync(0xffffffffu, sc, 4);
        sc += __shfl_xor_sync(0xffffffffu, sc, 2);
        sc += __shfl_xor_sync(0xffffffffu, sc, 1);
        sc += mask[SPAST];
        float nm   = fmaxf(m, sc);
        float corr = __expf(m - nm);
        float p    = __expf(sc - nm);
        m = nm;
        l = l * corr + p;
        acc.x = acc.x * corr + p * v4.x;
        acc.y = acc.y * corr + p * v4.y;
        acc.z = acc.z * corr + p * v4.z;
        acc.w = acc.w * corr + p * v4.w;
    }

    // Combine the 8 warps of this block.
    __shared__ float  sm_m[8], sm_l[8];
    __shared__ float4 sm_acc[8][32];
    sm_acc[warp][lane] = acc;
    if (lane == 0) { sm_m[warp] = m; sm_l[warp] = l; }
    __syncthreads();

    if (threadIdx.x < HD_) {
        int d = threadIdx.x;
        float M = -1e30f;
#pragma unroll
        for (int w = 0; w < 8; w++) M = fmaxf(M, sm_m[w]);
        float L = 0.f, A = 0.f;
        const float* accf = (const float*)sm_acc;
#pragma unroll
        for (int w = 0; w < 8; w++) {
            float e = __expf(sm_m[w] - M);
            L += sm_l[w] * e;
            A += accf[w * HD_ + d] * e;
        }
        int idx = bh * SPLITS + split;
        g_pacc[idx * HD_ + d] = A;
        if (d == 0) { g_pm[idx] = M; g_pl[idx] = L; }
    }
}

// ---------------------------------------------------------------------------
// Combine the 8 split partials per (b,h) AND seed the final output buffer
// with the Wo bias (256 blocks * 128 threads == 32768 == |out|), so the Wo
// split-K gemv can pure-atomicAdd with no separate init kernel.
// ---------------------------------------------------------------------------
__global__ __launch_bounds__(128) void attn_combine_kernel(
    float* __restrict__ out, const float* __restrict__ bo) {
    int bh = blockIdx.x;
    int d  = threadIdx.x;

    int oidx = bh * HD_ + d;          // [0, 32768)
    out[oidx] = bo[oidx & (D_ - 1)];  // seed Wo bias

    float M = -1e30f;
#pragma unroll
    for (int i = 0; i < SPLITS; i++) M = fmaxf(M, g_pm[bh * SPLITS + i]);
    float L = 0.f, A = 0.f;
#pragma unroll
    for (int i = 0; i < SPLITS; i++) {
        float e = __expf(g_pm[bh * SPLITS + i] - M);
        L += g_pl[bh * SPLITS + i] * e;
        A += g_pacc[(bh * SPLITS + i) * HD_ + d] * e;
    }
    int b = bh >> 4, h = bh & 15;
    g_attn[b * D_ + h * HD_ + d] = A / L;
}

// ---------------------------------------------------------------------------
extern "C" void kernel_launch(void* const* d_in, const int* in_sizes, int n_in,
                              void* d_out, int out_size) {
    const float* hs   = (const float*)d_in[0];
    const float* pk   = (const float*)d_in[1];
    const float* pv   = (const float*)d_in[2];
    const float* mask = (const float*)d_in[3];
    const float* Wq   = (const float*)d_in[4];
    const float* bq   = (const float*)d_in[5];
    const float* Wk   = (const float*)d_in[6];
    const float* bk   = (const float*)d_in[7];
    const float* Wv   = (const float*)d_in[8];
    const float* bv   = (const float*)d_in[9];
    const float* Wo   = (const float*)d_in[10];
    const float* bo   = (const float*)d_in[11];

    float* out  = (float*)d_out;          // [0, 32768): attn_output
    float* knew = out + B_ * D_;          // [32768, 65536): new_key
    float* vnew = out + 2 * B_ * D_;      // [65536, 98304): new_value

    float* qptr;  cudaGetSymbolAddress((void**)&qptr, g_q);
    float* aptr;  cudaGetSymbolAddress((void**)&aptr, g_attn);

    // 1. Fused QKV projection: 6144 rows / 16 = 384 blocks, direct bias store.
    GemvArgs a;
    a.W[0] = Wq; a.bias[0] = bq; a.out[0] = qptr; a.scale[0] = SCALING;
    a.W[1] = Wk; a.bias[1] = bk; a.out[1] = knew; a.scale[1] = 1.f;
    a.W[2] = Wv; a.bias[2] = bv; a.out[2] = vnew; a.scale[2] = 1.f;
    gemv_kernel<1><<<384, 256>>>(hs, a);

    // 2. Split-S attention partials (the HBM-bound 1.07 GB stream).
    attn_partial_kernel<<<dim3(B_ * H_, SPLITS), 256>>>(pk, pv, mask, knew, vnew);

    // 3. Combine partials + seed out with Wo bias.
    attn_combine_kernel<<<B_ * H_, 128>>>(out, bo);

    // 4. Output projection: 2048/16 = 128 blocks in x, split-K=4 -> 512 blocks.
    GemvArgs ao;
    ao.W[0] = Wo; ao.bias[0] = bo; ao.out[0] = out; ao.scale[0] = 1.f;
    ao.W[1] = Wo; ao.bias[1] = bo; ao.out[1] = out; ao.scale[1] = 1.f;
    ao.W[2] = Wo; ao.bias[2] = bo; ao.out[2] = out; ao.scale[2] = 1.f;
    gemv_kernel<4><<<dim3(128, 4), 256>>>(aptr, ao);
}